// round 14
// baseline (speedup 1.0000x reference)
#include <cuda_runtime.h>
#include <cuda_bf16.h>
#include <cstdint>

// Problem dims
#define BB    32
#define NNODE 512
#define FIN   256
#define HID   512
#define OUTC  512
#define NHEAD 4
#define DH    128
#define EPSV  1e-5f

#define KC    32          // k elements per smem stage
#define BUFSZ 32768       // AH|AL|BH|BL planes of 8KB each
#define NSTAGE 3

// ---------------- pre-split bf16 hi/lo planes (device globals) -------------
#define NX   ((size_t)16384 * 256)
#define NADJ ((size_t)512 * 512)
#define NGW  ((size_t)512 * 256)
#define NGAT ((size_t)512 * 512)
#define NCW  ((size_t)3 * 512 * 512)
#define SNO  ((size_t)512 * 512)          // 262144

__device__ __align__(16) __nv_bfloat16 g_xph[NX],   g_xpl[NX];
__device__ __align__(16) __nv_bfloat16 g_adjh[NADJ], g_adjl[NADJ];
__device__ __align__(16) __nv_bfloat16 g_gwth[NGW], g_gwtl[NGW];      // gc_w^T [512][256]
__device__ __align__(16) __nv_bfloat16 g_gath[NGAT], g_gatl[NGAT];    // gat_w [512][512]
__device__ __align__(16) __nv_bfloat16 g_cwh[NCW],  g_cwl[NCW];       // [kpos][co][ci]
__device__ __align__(16) __nv_bfloat16 g_suth[(size_t)512 * 16384], g_sutl[(size_t)512 * 16384];
__device__ __align__(16) __nv_bfloat16 g_gh[(size_t)BB * SNO],  g_gl[(size_t)BB * SNO];
__device__ __align__(16) __nv_bfloat16 g_hhh[(size_t)BB * SNO], g_hhl[(size_t)BB * SNO];
__device__ __align__(16) __nv_bfloat16 g_hth[(size_t)BB * SNO], g_htl[(size_t)BB * SNO];  // hh^T
__device__ __align__(16) __nv_bfloat16 g_ath[(size_t)128 * SNO], g_atl[(size_t)128 * SNO];
__device__ __align__(16) __nv_bfloat16 g_oh[(size_t)BB * SNO],  g_ol[(size_t)BB * SNO];
__device__ float g_att[(size_t)128 * SNO];    // fp32 logits

// ---------------------------------------------------------------------------
__device__ __forceinline__ void mma16816(float* c, const uint32_t* a, const uint32_t* b) {
    asm volatile(
        "mma.sync.aligned.m16n8k16.row.col.f32.bf16.bf16.f32 "
        "{%0,%1,%2,%3}, {%4,%5,%6,%7}, {%8,%9}, {%0,%1,%2,%3};"
        : "+f"(c[0]), "+f"(c[1]), "+f"(c[2]), "+f"(c[3])
        : "r"(a[0]), "r"(a[1]), "r"(a[2]), "r"(a[3]), "r"(b[0]), "r"(b[1]));
}
__device__ __forceinline__ void split_bf16(float x, __nv_bfloat16& h, __nv_bfloat16& l) {
    h = __float2bfloat16_rn(x);
    l = __float2bfloat16_rn(x - __bfloat162float(h));
}
__device__ __forceinline__ uint32_t sw_off(int row, int chunk) {
    return (uint32_t)((row << 6) + (((chunk) ^ ((row >> 1) & 3)) << 4));
}
__device__ __forceinline__ void ldm_x4(uint32_t& r0, uint32_t& r1, uint32_t& r2, uint32_t& r3,
                                       uint32_t a) {
    asm volatile("ldmatrix.sync.aligned.m8n8.x4.shared.b16 {%0,%1,%2,%3}, [%4];"
                 : "=r"(r0), "=r"(r1), "=r"(r2), "=r"(r3) : "r"(a));
}
__device__ __forceinline__ void cp16(uint32_t dst, const void* src, int sz) {
    asm volatile("cp.async.cg.shared.global [%0], [%1], 16, %2;"
                 :: "r"(dst), "l"(src), "r"(sz) : "memory");
}
__device__ __forceinline__ void cp_commit() {
    asm volatile("cp.async.commit_group;" ::: "memory");
}
template <int N>
__device__ __forceinline__ void cp_wait() {
    asm volatile("cp.async.wait_group %0;" :: "n"(N) : "memory");
}

#define TSTRIDE 136   // stash row stride in bf16 elems (272B, 16B-aligned)

// ---------------------------------------------------------------------------
// Pre-split GEMM, 3-stage cp.async ring, one barrier/step, B-frag reg pipeline.
// C = A @ B^T.  CONV: A rows shifted by (kpos-1), zero-padded; B +shift*SNO.
// EPI: 0 none, 1 (v+bias-m)*s+b then ReLU, 2 LeakyReLU(0.2)
// OUT: 0 = split bf16 planes, 1 = fp32, 2 = split planes + TRANSPOSED planes
// ---------------------------------------------------------------------------
template <int EPI, int OUT, bool CONV>
__global__ void __launch_bounds__(256, 2) gemm_p(
    const __nv_bfloat16* __restrict__ Ah, const __nv_bfloat16* __restrict__ Al,
    int lda, long sA1, long sA2,
    const __nv_bfloat16* __restrict__ Bh, const __nv_bfloat16* __restrict__ Bl,
    int ldb, long sB1, long sB2,
    float* __restrict__ Cf, __nv_bfloat16* __restrict__ Ch, __nv_bfloat16* __restrict__ Cl,
    int ldc, long sC1, long sC2,
    int K, int zdiv,
    const float* __restrict__ bias,
    const float* __restrict__ bng, const float* __restrict__ bnb,
    const float* __restrict__ bnm, const float* __restrict__ bnv,
    __nv_bfloat16* __restrict__ Th, __nv_bfloat16* __restrict__ Tl, int ldt, long sT1, long sT2)
{
    __shared__ __align__(16) unsigned char sm[NSTAGE * BUFSZ];
    const uint32_t smb = (uint32_t)__cvta_generic_to_shared(sm);

    const int z  = blockIdx.z;
    const int z1 = z / zdiv;
    const int z2 = z - z1 * zdiv;
    Ah += z1 * sA1 + z2 * sA2;  Al += z1 * sA1 + z2 * sA2;
    Bh += z1 * sB1 + z2 * sB2;  Bl += z1 * sB1 + z2 * sB2;
    if (OUT == 1) Cf += z1 * sC1 + z2 * sC2;
    else { Ch += z1 * sC1 + z2 * sC2; Cl += z1 * sC1 + z2 * sC2; }
    if (OUT == 2) { Th += z1 * sT1 + z2 * sT2; Tl += z1 * sT1 + z2 * sT2; }

    const int m0 = blockIdx.y * 128;
    const int n0 = blockIdx.x * 128;
    const int tid = threadIdx.x;

    const int w    = tid >> 5;
    const int lane = tid & 31;
    const int gq   = lane >> 2;
    const int tig  = lane & 3;
    const int wm   = (w >> 1) * 32;
    const int wn   = (w & 1) * 64;

    float acc[2][8][4];
#pragma unroll
    for (int i = 0; i < 2; i++)
#pragma unroll
        for (int j = 0; j < 8; j++)
#pragma unroll
            for (int q = 0; q < 4; q++) acc[i][j][q] = 0.f;

    const int steps = CONV ? 48 : (K >> 5);

    auto stageAsync = [&](int s, uint32_t bufo) {
        int k0, shift;
        if (CONV) { shift = s >> 4; k0 = (s & 15) * KC; }
        else      { shift = 0;      k0 = s * KC; }
        const uint32_t base = smb + bufo;
#pragma unroll
        for (int rep = 0; rep < 2; rep++) {
            const int c   = tid + rep * 256;
            const int row = c >> 2;
            const int kc  = c & 3;
            const uint32_t off = sw_off(row, kc);
            {
                long arow = m0 + row;
                int sz = 16;
                if (CONV) {
                    int rs = m0 + row + shift - 1;
                    if (rs < 0 || rs >= NNODE) { sz = 0; rs = 0; }
                    arow = rs;
                }
                const long so = arow * (long)lda + k0 + kc * 8;
                cp16(base + off,        Ah + so, sz);
                cp16(base + 8192 + off, Al + so, sz);
            }
            {
                const long so = (CONV ? (long)shift * (long)SNO : 0L)
                              + (long)(n0 + row) * (long)ldb + k0 + kc * 8;
                cp16(base + 16384 + off, Bh + so, 16);
                cp16(base + 24576 + off, Bl + so, 16);
            }
        }
    };

    auto compute = [&](uint32_t bufo) {
        const uint32_t AHs = smb + bufo, ALs = AHs + 8192;
        const uint32_t BHs = AHs + 16384, BLs = AHs + 24576;
#pragma unroll
        for (int ks = 0; ks < 2; ks++) {
            const int kc = ks * 2;
            uint32_t afh[2][4], afl[2][4];
            const int arow = wm + (lane & 15);
            const int achk = kc + (lane >> 4);
#pragma unroll
            for (int mt = 0; mt < 2; mt++) {
                const uint32_t off = sw_off(arow + mt * 16, achk);
                ldm_x4(afh[mt][0], afh[mt][1], afh[mt][2], afh[mt][3], AHs + off);
                ldm_x4(afl[mt][0], afl[mt][1], afl[mt][2], afl[mt][3], ALs + off);
            }
            const int brow_b = wn + (lane & 7) + ((lane >> 4) << 3);
            const int bchk = kc + ((lane >> 3) & 1);

            // register double-buffered B fragments: prefetch ntp+1 before
            // the MMA burst of ntp so LDSM latency is covered by ~24 MMAs.
            uint32_t bh[2][4], bl[2][4];
            {
                const uint32_t off0 = sw_off(brow_b, bchk);
                ldm_x4(bh[0][0], bh[0][1], bh[0][2], bh[0][3], BHs + off0);
                ldm_x4(bl[0][0], bl[0][1], bl[0][2], bl[0][3], BLs + off0);
            }
#pragma unroll
            for (int ntp = 0; ntp < 4; ntp++) {
                const int cur = ntp & 1, nxt = cur ^ 1;
                if (ntp < 3) {
                    const uint32_t offn = sw_off(brow_b + (ntp + 1) * 16, bchk);
                    ldm_x4(bh[nxt][0], bh[nxt][1], bh[nxt][2], bh[nxt][3], BHs + offn);
                    ldm_x4(bl[nxt][0], bl[nxt][1], bl[nxt][2], bl[nxt][3], BLs + offn);
                }
#pragma unroll
                for (int hf = 0; hf < 2; hf++) {
                    const int nt = ntp * 2 + hf;
                    uint32_t bfh[2] = {bh[cur][hf * 2], bh[cur][hf * 2 + 1]};
                    uint32_t bfl[2] = {bl[cur][hf * 2], bl[cur][hf * 2 + 1]};
#pragma unroll
                    for (int mt = 0; mt < 2; mt++) {
                        mma16816(acc[mt][nt], afh[mt], bfh);
                        mma16816(acc[mt][nt], afh[mt], bfl);
                        mma16816(acc[mt][nt], afl[mt], bfh);
                    }
                }
            }
        }
    };

    // ---- 3-stage ring, one barrier per step, prefetch before compute ----
    stageAsync(0, 0); cp_commit();
    stageAsync(1, BUFSZ); cp_commit();
    for (int s = 0; s < steps; s++) {
        cp_wait<1>();
        __syncthreads();
        if (s + 2 < steps) stageAsync(s + 2, (uint32_t)((s + 2) % NSTAGE) * BUFSZ);
        cp_commit();
        compute((uint32_t)(s % NSTAGE) * BUFSZ);
    }

    // ---- epilogue ----
    __nv_bfloat16* sth = reinterpret_cast<__nv_bfloat16*>(sm);
    __nv_bfloat16* stl = reinterpret_cast<__nv_bfloat16*>(sm + 128 * TSTRIDE * 2);
    if (OUT == 2) __syncthreads();

#pragma unroll
    for (int mt = 0; mt < 2; mt++) {
        const long r0 = m0 + wm + mt * 16 + gq;
        const long r1 = r0 + 8;
#pragma unroll
        for (int nt = 0; nt < 8; nt++) {
            const int cb = n0 + wn + nt * 8 + 2 * tig;
            float v[4] = {acc[mt][nt][0], acc[mt][nt][1], acc[mt][nt][2], acc[mt][nt][3]};
            if (EPI == 1) {
#pragma unroll
                for (int q = 0; q < 4; q++) {
                    const int n = cb + (q & 1);
                    float sc = bng[n] * rsqrtf(bnv[n] + EPSV);
                    v[q] = (v[q] + bias[n] - bnm[n]) * sc + bnb[n];
                    v[q] = fmaxf(v[q], 0.f);
                }
            } else if (EPI == 2) {
#pragma unroll
                for (int q = 0; q < 4; q++) v[q] = (v[q] > 0.f) ? v[q] : 0.2f * v[q];
            }
            if (OUT == 1) {
                *reinterpret_cast<float2*>(Cf + r0 * ldc + cb) = make_float2(v[0], v[1]);
                *reinterpret_cast<float2*>(Cf + r1 * ldc + cb) = make_float2(v[2], v[3]);
            } else {
                __nv_bfloat16 h0, l0, h1, l1, h2, l2, h3, l3;
                split_bf16(v[0], h0, l0); split_bf16(v[1], h1, l1);
                split_bf16(v[2], h2, l2); split_bf16(v[3], h3, l3);
                __nv_bfloat162 ph, pl;
                ph.x = h0; ph.y = h1; pl.x = l0; pl.y = l1;
                *reinterpret_cast<__nv_bfloat162*>(Ch + r0 * ldc + cb) = ph;
                *reinterpret_cast<__nv_bfloat162*>(Cl + r0 * ldc + cb) = pl;
                ph.x = h2; ph.y = h3; pl.x = l2; pl.y = l3;
                *reinterpret_cast<__nv_bfloat162*>(Ch + r1 * ldc + cb) = ph;
                *reinterpret_cast<__nv_bfloat162*>(Cl + r1 * ldc + cb) = pl;
                if (OUT == 2) {
                    const int lr0 = (int)(r0 - m0), lr1 = (int)(r1 - m0);
                    const int lc = cb - n0;
                    sth[(lc + 0) * TSTRIDE + lr0] = h0;
                    sth[(lc + 1) * TSTRIDE + lr0] = h1;
                    sth[(lc + 0) * TSTRIDE + lr1] = h2;
                    sth[(lc + 1) * TSTRIDE + lr1] = h3;
                    stl[(lc + 0) * TSTRIDE + lr0] = l0;
                    stl[(lc + 1) * TSTRIDE + lr0] = l1;
                    stl[(lc + 0) * TSTRIDE + lr1] = l2;
                    stl[(lc + 1) * TSTRIDE + lr1] = l3;
                }
            }
        }
    }

    if (OUT == 2) {
        __syncthreads();
        const int col  = tid >> 1;
        const int half = tid & 1;
        const long trow = (long)(n0 + col) * ldt + m0 + half * 64;
#pragma unroll
        for (int i = 0; i < 8; i++) {
            *reinterpret_cast<uint4*>(Th + trow + i * 8) =
                *reinterpret_cast<const uint4*>(&sth[col * TSTRIDE + half * 64 + i * 8]);
            *reinterpret_cast<uint4*>(Tl + trow + i * 8) =
                *reinterpret_cast<const uint4*>(&stl[col * TSTRIDE + half * 64 + i * 8]);
        }
    }
}

// ---------------------------------------------------------------------------
// prep: split raw fp32 inputs into bf16 hi/lo planes (vectorized, 4/thread)
// ---------------------------------------------------------------------------
__global__ void prep(const float* __restrict__ x, const float* __restrict__ adj,
                     const float* __restrict__ gc_w, const float* __restrict__ gat_w,
                     const float* __restrict__ conv_w)
{
    long i = ((long)blockIdx.x * 256 + threadIdx.x) * 4;
    __nv_bfloat16 h[4], l[4];

    auto storePlanes = [&](__nv_bfloat16* dh, __nv_bfloat16* dl, long idx) {
        __nv_bfloat162 p0, p1;
        p0.x = h[0]; p0.y = h[1]; p1.x = h[2]; p1.y = h[3];
        *reinterpret_cast<__nv_bfloat162*>(dh + idx)     = p0;
        *reinterpret_cast<__nv_bfloat162*>(dh + idx + 2) = p1;
        p0.x = l[0]; p0.y = l[1]; p1.x = l[2]; p1.y = l[3];
        *reinterpret_cast<__nv_bfloat162*>(dl + idx)     = p0;
        *reinterpret_cast<__nv_bfloat162*>(dl + idx + 2) = p1;
    };

    if (i < (long)NX) {
        float4 v = *reinterpret_cast<const float4*>(x + i);
        split_bf16(v.x, h[0], l[0]); split_bf16(v.y, h[1], l[1]);
        split_bf16(v.z, h[2], l[2]); split_bf16(v.w, h[3], l[3]);
        storePlanes(g_xph, g_xpl, i); return;
    }
    i -= NX;
    if (i < (long)NADJ) {
        float4 v = *reinterpret_cast<const float4*>(adj + i);
        split_bf16(v.x, h[0], l[0]); split_bf16(v.y, h[1], l[1]);
        split_bf16(v.z, h[2], l[2]); split_bf16(v.w, h[3], l[3]);
        storePlanes(g_adjh, g_adjl, i); return;
    }
    i -= NADJ;
    if (i < (long)NGW) {       // gwt[d][c] = gc_w[c][d]; 4 consecutive c
        long d = i >> 8, c = i & 255;
#pragma unroll
        for (int q = 0; q < 4; q++) split_bf16(gc_w[(c + q) * 512 + d], h[q], l[q]);
        storePlanes(g_gwth, g_gwtl, i); return;
    }
    i -= NGW;
    if (i < (long)NGAT) {
        float4 v = *reinterpret_cast<const float4*>(gat_w + i);
        split_bf16(v.x, h[0], l[0]); split_bf16(v.y, h[1], l[1]);
        split_bf16(v.z, h[2], l[2]); split_bf16(v.w, h[3], l[3]);
        storePlanes(g_gath, g_gatl, i); return;
    }
    i -= NGAT;
    if (i < (long)NCW) {       // cw[kpos][co][ci]; 4 consecutive ci
        long kpos = i / 262144, r = i % 262144;
        long co = r >> 9, ci = r & 511;
#pragma unroll
        for (int q = 0; q < 4; q++)
            split_bf16(conv_w[co * 1536 + (ci + q) * 3 + kpos], h[q], l[q]);
        storePlanes(g_cwh, g_cwl, i); return;
    }
}

// ---------------------------------------------------------------------------
// Row softmax over 512 fp32 -> split bf16 planes (shuffle reductions)
// ---------------------------------------------------------------------------
__global__ void softmax512(const float* __restrict__ att,
                           __nv_bfloat16* __restrict__ oh, __nv_bfloat16* __restrict__ ol)
{
    __shared__ float wmax[8], wsum[8];
    const long row = blockIdx.x;
    const float* p = att + row * 512;
    const int t = threadIdx.x;
    const int w = t >> 5, ln = t & 31;
    float a = p[t];
    float b = p[t + 256];
    float mx = fmaxf(a, b);
#pragma unroll
    for (int o = 16; o; o >>= 1) mx = fmaxf(mx, __shfl_xor_sync(0xffffffffu, mx, o));
    if (ln == 0) wmax[w] = mx;
    __syncthreads();
    float m = fmaxf(fmaxf(fmaxf(wmax[0], wmax[1]), fmaxf(wmax[2], wmax[3])),
                    fmaxf(fmaxf(wmax[4], wmax[5]), fmaxf(wmax[6], wmax[7])));
    float e0 = __expf(a - m);
    float e1 = __expf(b - m);
    float sm = e0 + e1;
#pragma unroll
    for (int o = 16; o; o >>= 1) sm += __shfl_xor_sync(0xffffffffu, sm, o);
    if (ln == 0) wsum[w] = sm;
    __syncthreads();
    float tot = (wsum[0] + wsum[1]) + (wsum[2] + wsum[3])
              + (wsum[4] + wsum[5]) + (wsum[6] + wsum[7]);
    const float inv = 1.f / tot;
    __nv_bfloat16 h, l;
    split_bf16(e0 * inv, h, l);
    oh[row * 512 + t] = h; ol[row * 512 + t] = l;
    split_bf16(e1 * inv, h, l);
    oh[row * 512 + t + 256] = h; ol[row * 512 + t + 256] = l;
}

// ---------------------------------------------------------------------------
extern "C" void kernel_launch(void* const* d_in, const int* in_sizes, int n_in,
                              void* d_out, int out_size)
{
    const float* x      = (const float*)d_in[0];
    const float* adj    = (const float*)d_in[1];
    const float* gc_w   = (const float*)d_in[2];
    const float* gc_b   = (const float*)d_in[3];
    const float* bn1g   = (const float*)d_in[4];
    const float* bn1b   = (const float*)d_in[5];
    const float* bn1m   = (const float*)d_in[6];
    const float* bn1v   = (const float*)d_in[7];
    const float* gat_w  = (const float*)d_in[8];
    const float* conv_w = (const float*)d_in[9];
    const float* conv_b = (const float*)d_in[10];
    const float* bn2g   = (const float*)d_in[11];
    const float* bn2b   = (const float*)d_in[12];
    const float* bn2m   = (const float*)d_in[13];
    const float* bn2v   = (const float*)d_in[14];
    float* out = (float*)d_out;

    __nv_bfloat16 *xph, *xpl, *adjh, *adjl, *gwth, *gwtl, *gath, *gatl, *cwh, *cwl;
    __nv_bfloat16 *suth, *sutl, *gh, *gl, *hhh, *hhl, *hth, *htl, *ath, *atl, *oh, *ol;
    float* att;
    cudaGetSymbolAddress((void**)&xph, g_xph);   cudaGetSymbolAddress((void**)&xpl, g_xpl);
    cudaGetSymbolAddress((void**)&adjh, g_adjh); cudaGetSymbolAddress((void**)&adjl, g_adjl);
    cudaGetSymbolAddress((void**)&gwth, g_gwth); cudaGetSymbolAddress((void**)&gwtl, g_gwtl);
    cudaGetSymbolAddress((void**)&gath, g_gath); cudaGetSymbolAddress((void**)&gatl, g_gatl);
    cudaGetSymbolAddress((void**)&cwh, g_cwh);   cudaGetSymbolAddress((void**)&cwl, g_cwl);
    cudaGetSymbolAddress((void**)&suth, g_suth); cudaGetSymbolAddress((void**)&sutl, g_sutl);
    cudaGetSymbolAddress((void**)&gh, g_gh);     cudaGetSymbolAddress((void**)&gl, g_gl);
    cudaGetSymbolAddress((void**)&hhh, g_hhh);   cudaGetSymbolAddress((void**)&hhl, g_hhl);
    cudaGetSymbolAddress((void**)&hth, g_hth);   cudaGetSymbolAddress((void**)&htl, g_htl);
    cudaGetSymbolAddress((void**)&ath, g_ath);   cudaGetSymbolAddress((void**)&atl, g_atl);
    cudaGetSymbolAddress((void**)&oh, g_oh);     cudaGetSymbolAddress((void**)&ol, g_ol);
    cudaGetSymbolAddress((void**)&att, g_att);

    const long total_prep = (long)(NX + NADJ + NGW + NGAT + NCW);

    // 0) split inputs (4 elems/thread)
    prep<<<(unsigned)((total_prep / 4 + 255) / 256), 256>>>(x, adj, gc_w, gat_w, conv_w);

    // 1) supT[d][bn] = sum_c gwt[d][c] * x[bn][c]
    gemm_p<0, 0, false><<<dim3(128, 4, 1), 256>>>(
        gwth, gwtl, 256, 0, 0,
        xph, xpl, 256, 0, 0,
        nullptr, suth, sutl, 16384, 0, 0,
        256, 1, nullptr, nullptr, nullptr, nullptr, nullptr,
        nullptr, nullptr, 0, 0, 0);

    // 2) g[b] = relu(bn1(adj @ sup + gc_b))
    gemm_p<1, 0, false><<<dim3(4, 4, BB), 256>>>(
        adjh, adjl, 512, 0, 0,
        suth, sutl, 16384, 512, 0,
        nullptr, gh, gl, 512, (long)SNO, 0,
        512, 1, gc_b, bn1g, bn1b, bn1m, bn1v,
        nullptr, nullptr, 0, 0, 0);

    // 3) hh[b] = g @ gat_w^T   (+ fused transpose -> hhT)
    gemm_p<0, 2, false><<<dim3(4, 4, BB), 256>>>(
        gh, gl, 512, (long)SNO, 0,
        gath, gatl, 512, 0, 0,
        nullptr, hhh, hhl, 512, (long)SNO, 0,
        512, 1, nullptr, nullptr, nullptr, nullptr, nullptr,
        hth, htl, 512, (long)SNO, 0);

    // 4) logits[b,h] = leaky(hh_h @ hh_h^T)
    gemm_p<2, 1, false><<<dim3(4, 4, BB * NHEAD), 256>>>(
        hhh, hhl, 512, (long)SNO, 128,
        hhh, hhl, 512, (long)SNO, 128,
        att, nullptr, nullptr, 512, (long)(4 * SNO), (long)SNO,
        128, NHEAD, nullptr, nullptr, nullptr, nullptr, nullptr,
        nullptr, nullptr, 0, 0, 0);

    // 5) softmax -> split att planes
    softmax512<<<128 * 512, 256>>>(att, ath, atl);

    // 6) o[b,h] = att @ hh_h
    gemm_p<0, 0, false><<<dim3(1, 4, BB * NHEAD), 256>>>(
        ath, atl, 512, (long)(4 * SNO), (long)SNO,
        hth, htl, 512, (long)SNO, (long)(128 * 512),
        nullptr, oh, ol, 512, (long)SNO, 128,
        512, NHEAD, nullptr, nullptr, nullptr, nullptr, nullptr,
        nullptr, nullptr, 0, 0, 0);

    // 7) conv1d(k=3,p=1) + bias + bn2 + relu -> out fp32
    gemm_p<1, 1, true><<<dim3(4, 4, BB), 256>>>(
        oh, ol, 512, (long)SNO, 0,
        cwh, cwl, 512, 0, 0,
        out, nullptr, nullptr, 512, (long)SNO, 0,
        3 * 512, 1, conv_b, bn2g, bn2b, bn2m, bn2v,
        nullptr, nullptr, 0, 0, 0);
}

// round 15
// speedup vs baseline: 1.5223x; 1.5223x over previous
#include <cuda_runtime.h>
#include <cuda_bf16.h>
#include <cstdint>

// Problem dims
#define BB    32
#define NNODE 512
#define FIN   256
#define HID   512
#define OUTC  512
#define NHEAD 4
#define DH    128
#define EPSV  1e-5f

#define KC    32          // k elements per smem stage
#define BUFSZ 32768       // AH|AL|BH|BL planes of 8KB each
#define NSTAGE 3

// ---------------- pre-split bf16 hi/lo planes (device globals) -------------
#define NX   ((size_t)16384 * 256)
#define NADJ ((size_t)512 * 512)
#define NGW  ((size_t)512 * 256)
#define NGAT ((size_t)512 * 512)
#define NCW  ((size_t)3 * 512 * 512)
#define SNO  ((size_t)512 * 512)          // 262144

__device__ __align__(16) __nv_bfloat16 g_xph[NX],   g_xpl[NX];
__device__ __align__(16) __nv_bfloat16 g_adjh[NADJ], g_adjl[NADJ];
__device__ __align__(16) __nv_bfloat16 g_gwth[NGW], g_gwtl[NGW];      // gc_w^T [512][256]
__device__ __align__(16) __nv_bfloat16 g_gath[NGAT], g_gatl[NGAT];    // gat_w [512][512]
__device__ __align__(16) __nv_bfloat16 g_cwh[NCW],  g_cwl[NCW];       // [kpos][co][ci]
__device__ __align__(16) __nv_bfloat16 g_suth[(size_t)512 * 16384], g_sutl[(size_t)512 * 16384];
__device__ __align__(16) __nv_bfloat16 g_gh[(size_t)BB * SNO],  g_gl[(size_t)BB * SNO];
__device__ __align__(16) __nv_bfloat16 g_hhh[(size_t)BB * SNO], g_hhl[(size_t)BB * SNO];
__device__ __align__(16) __nv_bfloat16 g_hth[(size_t)BB * SNO], g_htl[(size_t)BB * SNO];  // hh^T
__device__ __align__(16) __nv_bfloat16 g_ath[(size_t)128 * SNO], g_atl[(size_t)128 * SNO];
__device__ __align__(16) __nv_bfloat16 g_oh[(size_t)BB * SNO],  g_ol[(size_t)BB * SNO];
__device__ float g_att[(size_t)128 * SNO];    // fp32 logits

// ---------------------------------------------------------------------------
__device__ __forceinline__ void mma16816(float* c, const uint32_t* a, const uint32_t* b) {
    asm volatile(
        "mma.sync.aligned.m16n8k16.row.col.f32.bf16.bf16.f32 "
        "{%0,%1,%2,%3}, {%4,%5,%6,%7}, {%8,%9}, {%0,%1,%2,%3};"
        : "+f"(c[0]), "+f"(c[1]), "+f"(c[2]), "+f"(c[3])
        : "r"(a[0]), "r"(a[1]), "r"(a[2]), "r"(a[3]), "r"(b[0]), "r"(b[1]));
}
__device__ __forceinline__ void split_bf16(float x, __nv_bfloat16& h, __nv_bfloat16& l) {
    h = __float2bfloat16_rn(x);
    l = __float2bfloat16_rn(x - __bfloat162float(h));
}
__device__ __forceinline__ uint32_t sw_off(int row, int chunk) {
    return (uint32_t)((row << 6) + (((chunk) ^ ((row >> 1) & 3)) << 4));
}
__device__ __forceinline__ void ldm_x4(uint32_t& r0, uint32_t& r1, uint32_t& r2, uint32_t& r3,
                                       uint32_t a) {
    asm volatile("ldmatrix.sync.aligned.m8n8.x4.shared.b16 {%0,%1,%2,%3}, [%4];"
                 : "=r"(r0), "=r"(r1), "=r"(r2), "=r"(r3) : "r"(a));
}
__device__ __forceinline__ void cp16(uint32_t dst, const void* src, int sz) {
    asm volatile("cp.async.cg.shared.global [%0], [%1], 16, %2;"
                 :: "r"(dst), "l"(src), "r"(sz) : "memory");
}
__device__ __forceinline__ void cp_commit() {
    asm volatile("cp.async.commit_group;" ::: "memory");
}
template <int N>
__device__ __forceinline__ void cp_wait() {
    asm volatile("cp.async.wait_group %0;" :: "n"(N) : "memory");
}

#define TSTRIDE 136   // stash row stride in bf16 elems (272B, 16B-aligned)

// ---------------------------------------------------------------------------
// Pre-split GEMM, 3-stage cp.async ring, one barrier/step (R13 structure).
// MMA bursts are pass-outer ordered: 4 independent MMAs between writes to
// the same accumulator (register-neutral de-chaining).
// C = A @ B^T.  CONV: A rows shifted by (kpos-1), zero-padded; B +shift*SNO.
// EPI: 0 none, 1 (v+bias-m)*s+b then ReLU, 2 LeakyReLU(0.2)
// OUT: 0 = split bf16 planes, 1 = fp32, 2 = split planes + TRANSPOSED planes
// ---------------------------------------------------------------------------
template <int EPI, int OUT, bool CONV>
__global__ void __launch_bounds__(256, 2) gemm_p(
    const __nv_bfloat16* __restrict__ Ah, const __nv_bfloat16* __restrict__ Al,
    int lda, long sA1, long sA2,
    const __nv_bfloat16* __restrict__ Bh, const __nv_bfloat16* __restrict__ Bl,
    int ldb, long sB1, long sB2,
    float* __restrict__ Cf, __nv_bfloat16* __restrict__ Ch, __nv_bfloat16* __restrict__ Cl,
    int ldc, long sC1, long sC2,
    int K, int zdiv,
    const float* __restrict__ bias,
    const float* __restrict__ bng, const float* __restrict__ bnb,
    const float* __restrict__ bnm, const float* __restrict__ bnv,
    __nv_bfloat16* __restrict__ Th, __nv_bfloat16* __restrict__ Tl, int ldt, long sT1, long sT2)
{
    __shared__ __align__(16) unsigned char sm[NSTAGE * BUFSZ];
    const uint32_t smb = (uint32_t)__cvta_generic_to_shared(sm);

    const int z  = blockIdx.z;
    const int z1 = z / zdiv;
    const int z2 = z - z1 * zdiv;
    Ah += z1 * sA1 + z2 * sA2;  Al += z1 * sA1 + z2 * sA2;
    Bh += z1 * sB1 + z2 * sB2;  Bl += z1 * sB1 + z2 * sB2;
    if (OUT == 1) Cf += z1 * sC1 + z2 * sC2;
    else { Ch += z1 * sC1 + z2 * sC2; Cl += z1 * sC1 + z2 * sC2; }
    if (OUT == 2) { Th += z1 * sT1 + z2 * sT2; Tl += z1 * sT1 + z2 * sT2; }

    const int m0 = blockIdx.y * 128;
    const int n0 = blockIdx.x * 128;
    const int tid = threadIdx.x;

    const int w    = tid >> 5;
    const int lane = tid & 31;
    const int gq   = lane >> 2;
    const int tig  = lane & 3;
    const int wm   = (w >> 1) * 32;
    const int wn   = (w & 1) * 64;

    float acc[2][8][4];
#pragma unroll
    for (int i = 0; i < 2; i++)
#pragma unroll
        for (int j = 0; j < 8; j++)
#pragma unroll
            for (int q = 0; q < 4; q++) acc[i][j][q] = 0.f;

    const int steps = CONV ? 48 : (K >> 5);

    auto stageAsync = [&](int s, uint32_t bufo) {
        int k0, shift;
        if (CONV) { shift = s >> 4; k0 = (s & 15) * KC; }
        else      { shift = 0;      k0 = s * KC; }
        const uint32_t base = smb + bufo;
#pragma unroll
        for (int rep = 0; rep < 2; rep++) {
            const int c   = tid + rep * 256;
            const int row = c >> 2;
            const int kc  = c & 3;
            const uint32_t off = sw_off(row, kc);
            {
                long arow = m0 + row;
                int sz = 16;
                if (CONV) {
                    int rs = m0 + row + shift - 1;
                    if (rs < 0 || rs >= NNODE) { sz = 0; rs = 0; }
                    arow = rs;
                }
                const long so = arow * (long)lda + k0 + kc * 8;
                cp16(base + off,        Ah + so, sz);
                cp16(base + 8192 + off, Al + so, sz);
            }
            {
                const long so = (CONV ? (long)shift * (long)SNO : 0L)
                              + (long)(n0 + row) * (long)ldb + k0 + kc * 8;
                cp16(base + 16384 + off, Bh + so, 16);
                cp16(base + 24576 + off, Bl + so, 16);
            }
        }
    };

    auto compute = [&](uint32_t bufo) {
        const uint32_t AHs = smb + bufo, ALs = AHs + 8192;
        const uint32_t BHs = AHs + 16384, BLs = AHs + 24576;
#pragma unroll
        for (int ks = 0; ks < 2; ks++) {
            const int kc = ks * 2;
            uint32_t afh[2][4], afl[2][4];
            const int arow = wm + (lane & 15);
            const int achk = kc + (lane >> 4);
#pragma unroll
            for (int mt = 0; mt < 2; mt++) {
                const uint32_t off = sw_off(arow + mt * 16, achk);
                ldm_x4(afh[mt][0], afh[mt][1], afh[mt][2], afh[mt][3], AHs + off);
                ldm_x4(afl[mt][0], afl[mt][1], afl[mt][2], afl[mt][3], ALs + off);
            }
            const int brow_b = wn + (lane & 7) + ((lane >> 4) << 3);
            const int bchk = kc + ((lane >> 3) & 1);
#pragma unroll
            for (int ntp = 0; ntp < 4; ntp++) {
                const uint32_t off = sw_off(brow_b + ntp * 16, bchk);
                uint32_t bh[4], bl[4];
                ldm_x4(bh[0], bh[1], bh[2], bh[3], BHs + off);
                ldm_x4(bl[0], bl[1], bl[2], bl[3], BLs + off);
                // pass-outer ordering: same-acc MMAs are 4 apart.
                // Per-acc order stays hh -> hl -> lh (bit-identical).
#pragma unroll
                for (int pass = 0; pass < 3; pass++) {
#pragma unroll
                    for (int hf = 0; hf < 2; hf++) {
                        const int nt = ntp * 2 + hf;
                        uint32_t bfh[2] = {bh[hf * 2], bh[hf * 2 + 1]};
                        uint32_t bfl[2] = {bl[hf * 2], bl[hf * 2 + 1]};
#pragma unroll
                        for (int mt = 0; mt < 2; mt++) {
                            if (pass == 0)      mma16816(acc[mt][nt], afh[mt], bfh);
                            else if (pass == 1) mma16816(acc[mt][nt], afh[mt], bfl);
                            else                mma16816(acc[mt][nt], afl[mt], bfh);
                        }
                    }
                }
            }
        }
    };

    // ---- 3-stage ring, one barrier per step, prefetch before compute ----
    stageAsync(0, 0); cp_commit();
    stageAsync(1, BUFSZ); cp_commit();
    for (int s = 0; s < steps; s++) {
        cp_wait<1>();
        __syncthreads();
        if (s + 2 < steps) stageAsync(s + 2, (uint32_t)((s + 2) % NSTAGE) * BUFSZ);
        cp_commit();
        compute((uint32_t)(s % NSTAGE) * BUFSZ);
    }

    // ---- epilogue ----
    __nv_bfloat16* sth = reinterpret_cast<__nv_bfloat16*>(sm);
    __nv_bfloat16* stl = reinterpret_cast<__nv_bfloat16*>(sm + 128 * TSTRIDE * 2);
    if (OUT == 2) __syncthreads();

#pragma unroll
    for (int mt = 0; mt < 2; mt++) {
        const long r0 = m0 + wm + mt * 16 + gq;
        const long r1 = r0 + 8;
#pragma unroll
        for (int nt = 0; nt < 8; nt++) {
            const int cb = n0 + wn + nt * 8 + 2 * tig;
            float v[4] = {acc[mt][nt][0], acc[mt][nt][1], acc[mt][nt][2], acc[mt][nt][3]};
            if (EPI == 1) {
#pragma unroll
                for (int q = 0; q < 4; q++) {
                    const int n = cb + (q & 1);
                    float sc = bng[n] * rsqrtf(bnv[n] + EPSV);
                    v[q] = (v[q] + bias[n] - bnm[n]) * sc + bnb[n];
                    v[q] = fmaxf(v[q], 0.f);
                }
            } else if (EPI == 2) {
#pragma unroll
                for (int q = 0; q < 4; q++) v[q] = (v[q] > 0.f) ? v[q] : 0.2f * v[q];
            }
            if (OUT == 1) {
                *reinterpret_cast<float2*>(Cf + r0 * ldc + cb) = make_float2(v[0], v[1]);
                *reinterpret_cast<float2*>(Cf + r1 * ldc + cb) = make_float2(v[2], v[3]);
            } else {
                __nv_bfloat16 h0, l0, h1, l1, h2, l2, h3, l3;
                split_bf16(v[0], h0, l0); split_bf16(v[1], h1, l1);
                split_bf16(v[2], h2, l2); split_bf16(v[3], h3, l3);
                __nv_bfloat162 ph, pl;
                ph.x = h0; ph.y = h1; pl.x = l0; pl.y = l1;
                *reinterpret_cast<__nv_bfloat162*>(Ch + r0 * ldc + cb) = ph;
                *reinterpret_cast<__nv_bfloat162*>(Cl + r0 * ldc + cb) = pl;
                ph.x = h2; ph.y = h3; pl.x = l2; pl.y = l3;
                *reinterpret_cast<__nv_bfloat162*>(Ch + r1 * ldc + cb) = ph;
                *reinterpret_cast<__nv_bfloat162*>(Cl + r1 * ldc + cb) = pl;
                if (OUT == 2) {
                    const int lr0 = (int)(r0 - m0), lr1 = (int)(r1 - m0);
                    const int lc = cb - n0;
                    sth[(lc + 0) * TSTRIDE + lr0] = h0;
                    sth[(lc + 1) * TSTRIDE + lr0] = h1;
                    sth[(lc + 0) * TSTRIDE + lr1] = h2;
                    sth[(lc + 1) * TSTRIDE + lr1] = h3;
                    stl[(lc + 0) * TSTRIDE + lr0] = l0;
                    stl[(lc + 1) * TSTRIDE + lr0] = l1;
                    stl[(lc + 0) * TSTRIDE + lr1] = l2;
                    stl[(lc + 1) * TSTRIDE + lr1] = l3;
                }
            }
        }
    }

    if (OUT == 2) {
        __syncthreads();
        const int col  = tid >> 1;
        const int half = tid & 1;
        const long trow = (long)(n0 + col) * ldt + m0 + half * 64;
#pragma unroll
        for (int i = 0; i < 8; i++) {
            *reinterpret_cast<uint4*>(Th + trow + i * 8) =
                *reinterpret_cast<const uint4*>(&sth[col * TSTRIDE + half * 64 + i * 8]);
            *reinterpret_cast<uint4*>(Tl + trow + i * 8) =
                *reinterpret_cast<const uint4*>(&stl[col * TSTRIDE + half * 64 + i * 8]);
        }
    }
}

// ---------------------------------------------------------------------------
// prep: split raw fp32 inputs into bf16 hi/lo planes (vectorized, 4/thread)
// ---------------------------------------------------------------------------
__global__ void prep(const float* __restrict__ x, const float* __restrict__ adj,
                     const float* __restrict__ gc_w, const float* __restrict__ gat_w,
                     const float* __restrict__ conv_w)
{
    long i = ((long)blockIdx.x * 256 + threadIdx.x) * 4;
    __nv_bfloat16 h[4], l[4];

    auto storePlanes = [&](__nv_bfloat16* dh, __nv_bfloat16* dl, long idx) {
        __nv_bfloat162 p0, p1;
        p0.x = h[0]; p0.y = h[1]; p1.x = h[2]; p1.y = h[3];
        *reinterpret_cast<__nv_bfloat162*>(dh + idx)     = p0;
        *reinterpret_cast<__nv_bfloat162*>(dh + idx + 2) = p1;
        p0.x = l[0]; p0.y = l[1]; p1.x = l[2]; p1.y = l[3];
        *reinterpret_cast<__nv_bfloat162*>(dl + idx)     = p0;
        *reinterpret_cast<__nv_bfloat162*>(dl + idx + 2) = p1;
    };

    if (i < (long)NX) {
        float4 v = *reinterpret_cast<const float4*>(x + i);
        split_bf16(v.x, h[0], l[0]); split_bf16(v.y, h[1], l[1]);
        split_bf16(v.z, h[2], l[2]); split_bf16(v.w, h[3], l[3]);
        storePlanes(g_xph, g_xpl, i); return;
    }
    i -= NX;
    if (i < (long)NADJ) {
        float4 v = *reinterpret_cast<const float4*>(adj + i);
        split_bf16(v.x, h[0], l[0]); split_bf16(v.y, h[1], l[1]);
        split_bf16(v.z, h[2], l[2]); split_bf16(v.w, h[3], l[3]);
        storePlanes(g_adjh, g_adjl, i); return;
    }
    i -= NADJ;
    if (i < (long)NGW) {       // gwt[d][c] = gc_w[c][d]; 4 consecutive c
        long d = i >> 8, c = i & 255;
#pragma unroll
        for (int q = 0; q < 4; q++) split_bf16(gc_w[(c + q) * 512 + d], h[q], l[q]);
        storePlanes(g_gwth, g_gwtl, i); return;
    }
    i -= NGW;
    if (i < (long)NGAT) {
        float4 v = *reinterpret_cast<const float4*>(gat_w + i);
        split_bf16(v.x, h[0], l[0]); split_bf16(v.y, h[1], l[1]);
        split_bf16(v.z, h[2], l[2]); split_bf16(v.w, h[3], l[3]);
        storePlanes(g_gath, g_gatl, i); return;
    }
    i -= NGAT;
    if (i < (long)NCW) {       // cw[kpos][co][ci]; 4 consecutive ci
        long kpos = i / 262144, r = i % 262144;
        long co = r >> 9, ci = r & 511;
#pragma unroll
        for (int q = 0; q < 4; q++)
            split_bf16(conv_w[co * 1536 + (ci + q) * 3 + kpos], h[q], l[q]);
        storePlanes(g_cwh, g_cwl, i); return;
    }
}

// ---------------------------------------------------------------------------
// Row softmax over 512 fp32 -> split bf16 planes (shuffle reductions)
// ---------------------------------------------------------------------------
__global__ void softmax512(const float* __restrict__ att,
                           __nv_bfloat16* __restrict__ oh, __nv_bfloat16* __restrict__ ol)
{
    __shared__ float wmax[8], wsum[8];
    const long row = blockIdx.x;
    const float* p = att + row * 512;
    const int t = threadIdx.x;
    const int w = t >> 5, ln = t & 31;
    float a = p[t];
    float b = p[t + 256];
    float mx = fmaxf(a, b);
#pragma unroll
    for (int o = 16; o; o >>= 1) mx = fmaxf(mx, __shfl_xor_sync(0xffffffffu, mx, o));
    if (ln == 0) wmax[w] = mx;
    __syncthreads();
    float m = fmaxf(fmaxf(fmaxf(wmax[0], wmax[1]), fmaxf(wmax[2], wmax[3])),
                    fmaxf(fmaxf(wmax[4], wmax[5]), fmaxf(wmax[6], wmax[7])));
    float e0 = __expf(a - m);
    float e1 = __expf(b - m);
    float sm = e0 + e1;
#pragma unroll
    for (int o = 16; o; o >>= 1) sm += __shfl_xor_sync(0xffffffffu, sm, o);
    if (ln == 0) wsum[w] = sm;
    __syncthreads();
    float tot = (wsum[0] + wsum[1]) + (wsum[2] + wsum[3])
              + (wsum[4] + wsum[5]) + (wsum[6] + wsum[7]);
    const float inv = 1.f / tot;
    __nv_bfloat16 h, l;
    split_bf16(e0 * inv, h, l);
    oh[row * 512 + t] = h; ol[row * 512 + t] = l;
    split_bf16(e1 * inv, h, l);
    oh[row * 512 + t + 256] = h; ol[row * 512 + t + 256] = l;
}

// ---------------------------------------------------------------------------
extern "C" void kernel_launch(void* const* d_in, const int* in_sizes, int n_in,
                              void* d_out, int out_size)
{
    const float* x      = (const float*)d_in[0];
    const float* adj    = (const float*)d_in[1];
    const float* gc_w   = (const float*)d_in[2];
    const float* gc_b   = (const float*)d_in[3];
    const float* bn1g   = (const float*)d_in[4];
    const float* bn1b   = (const float*)d_in[5];
    const float* bn1m   = (const float*)d_in[6];
    const float* bn1v   = (const float*)d_in[7];
    const float* gat_w  = (const float*)d_in[8];
    const float* conv_w = (const float*)d_in[9];
    const float* conv_b = (const float*)d_in[10];
    const float* bn2g   = (const float*)d_in[11];
    const float* bn2b   = (const float*)d_in[12];
    const float* bn2m   = (const float*)d_in[13];
    const float* bn2v   = (const float*)d_in[14];
    float* out = (float*)d_out;

    __nv_bfloat16 *xph, *xpl, *adjh, *adjl, *gwth, *gwtl, *gath, *gatl, *cwh, *cwl;
    __nv_bfloat16 *suth, *sutl, *gh, *gl, *hhh, *hhl, *hth, *htl, *ath, *atl, *oh, *ol;
    float* att;
    cudaGetSymbolAddress((void**)&xph, g_xph);   cudaGetSymbolAddress((void**)&xpl, g_xpl);
    cudaGetSymbolAddress((void**)&adjh, g_adjh); cudaGetSymbolAddress((void**)&adjl, g_adjl);
    cudaGetSymbolAddress((void**)&gwth, g_gwth); cudaGetSymbolAddress((void**)&gwtl, g_gwtl);
    cudaGetSymbolAddress((void**)&gath, g_gath); cudaGetSymbolAddress((void**)&gatl, g_gatl);
    cudaGetSymbolAddress((void**)&cwh, g_cwh);   cudaGetSymbolAddress((void**)&cwl, g_cwl);
    cudaGetSymbolAddress((void**)&suth, g_suth); cudaGetSymbolAddress((void**)&sutl, g_sutl);
    cudaGetSymbolAddress((void**)&gh, g_gh);     cudaGetSymbolAddress((void**)&gl, g_gl);
    cudaGetSymbolAddress((void**)&hhh, g_hhh);   cudaGetSymbolAddress((void**)&hhl, g_hhl);
    cudaGetSymbolAddress((void**)&hth, g_hth);   cudaGetSymbolAddress((void**)&htl, g_htl);
    cudaGetSymbolAddress((void**)&ath, g_ath);   cudaGetSymbolAddress((void**)&atl, g_atl);
    cudaGetSymbolAddress((void**)&oh, g_oh);     cudaGetSymbolAddress((void**)&ol, g_ol);
    cudaGetSymbolAddress((void**)&att, g_att);

    const long total_prep = (long)(NX + NADJ + NGW + NGAT + NCW);

    // 0) split inputs (4 elems/thread)
    prep<<<(unsigned)((total_prep / 4 + 255) / 256), 256>>>(x, adj, gc_w, gat_w, conv_w);

    // 1) supT[d][bn] = sum_c gwt[d][c] * x[bn][c]
    gemm_p<0, 0, false><<<dim3(128, 4, 1), 256>>>(
        gwth, gwtl, 256, 0, 0,
        xph, xpl, 256, 0, 0,
        nullptr, suth, sutl, 16384, 0, 0,
        256, 1, nullptr, nullptr, nullptr, nullptr, nullptr,
        nullptr, nullptr, 0, 0, 0);

    // 2) g[b] = relu(bn1(adj @ sup + gc_b))
    gemm_p<1, 0, false><<<dim3(4, 4, BB), 256>>>(
        adjh, adjl, 512, 0, 0,
        suth, sutl, 16384, 512, 0,
        nullptr, gh, gl, 512, (long)SNO, 0,
        512, 1, gc_b, bn1g, bn1b, bn1m, bn1v,
        nullptr, nullptr, 0, 0, 0);

    // 3) hh[b] = g @ gat_w^T   (+ fused transpose -> hhT)
    gemm_p<0, 2, false><<<dim3(4, 4, BB), 256>>>(
        gh, gl, 512, (long)SNO, 0,
        gath, gatl, 512, 0, 0,
        nullptr, hhh, hhl, 512, (long)SNO, 0,
        512, 1, nullptr, nullptr, nullptr, nullptr, nullptr,
        hth, htl, 512, (long)SNO, 0);

    // 4) logits[b,h] = leaky(hh_h @ hh_h^T)
    gemm_p<2, 1, false><<<dim3(4, 4, BB * NHEAD), 256>>>(
        hhh, hhl, 512, (long)SNO, 128,
        hhh, hhl, 512, (long)SNO, 128,
        att, nullptr, nullptr, 512, (long)(4 * SNO), (long)SNO,
        128, NHEAD, nullptr, nullptr, nullptr, nullptr, nullptr,
        nullptr, nullptr, 0, 0, 0);

    // 5) softmax -> split att planes
    softmax512<<<128 * 512, 256>>>(att, ath, atl);

    // 6) o[b,h] = att @ hh_h
    gemm_p<0, 0, false><<<dim3(1, 4, BB * NHEAD), 256>>>(
        ath, atl, 512, (long)(4 * SNO), (long)SNO,
        hth, htl, 512, (long)SNO, (long)(128 * 512),
        nullptr, oh, ol, 512, (long)SNO, 128,
        512, NHEAD, nullptr, nullptr, nullptr, nullptr, nullptr,
        nullptr, nullptr, 0, 0, 0);

    // 7) conv1d(k=3,p=1) + bias + bn2 + relu -> out fp32
    gemm_p<1, 1, true><<<dim3(4, 4, BB), 256>>>(
        oh, ol, 512, (long)SNO, 0,
        cwh, cwl, 512, 0, 0,
        out, nullptr, nullptr, 512, (long)SNO, 0,
        3 * 512, 1, conv_b, bn2g, bn2b, bn2m, bn2v,
        nullptr, nullptr, 0, 0, 0);
}

// round 17
// speedup vs baseline: 1.6630x; 1.0925x over previous
#include <cuda_runtime.h>
#include <cuda_bf16.h>
#include <cstdint>

// Problem dims
#define BB    32
#define NNODE 512
#define FIN   256
#define HID   512
#define OUTC  512
#define NHEAD 4
#define DH    128
#define EPSV  1e-5f

#define KC    32          // k elements per smem stage
// planes: AH 8KB | AL 8KB | BH 4KB | BL 4KB  (tile 128m x 64n)
#define BUFSZ 24576
#define NSTAGE 3

// ---------------- pre-split bf16 hi/lo planes (device globals) -------------
#define NX   ((size_t)16384 * 256)
#define NADJ ((size_t)512 * 512)
#define NGW  ((size_t)512 * 256)
#define NGAT ((size_t)512 * 512)
#define NCW  ((size_t)3 * 512 * 512)
#define SNO  ((size_t)512 * 512)          // 262144

__device__ __align__(16) __nv_bfloat16 g_xph[NX],   g_xpl[NX];
__device__ __align__(16) __nv_bfloat16 g_adjh[NADJ], g_adjl[NADJ];
__device__ __align__(16) __nv_bfloat16 g_gwth[NGW], g_gwtl[NGW];      // gc_w^T [512][256]
__device__ __align__(16) __nv_bfloat16 g_gath[NGAT], g_gatl[NGAT];    // gat_w [512][512]
__device__ __align__(16) __nv_bfloat16 g_cwh[NCW],  g_cwl[NCW];       // [kpos][co][ci]
__device__ __align__(16) __nv_bfloat16 g_suth[(size_t)512 * 16384], g_sutl[(size_t)512 * 16384];
__device__ __align__(16) __nv_bfloat16 g_gh[(size_t)BB * SNO],  g_gl[(size_t)BB * SNO];
__device__ __align__(16) __nv_bfloat16 g_hhh[(size_t)BB * SNO], g_hhl[(size_t)BB * SNO];
__device__ __align__(16) __nv_bfloat16 g_hth[(size_t)BB * SNO], g_htl[(size_t)BB * SNO];  // hh^T
__device__ __align__(16) __nv_bfloat16 g_ath[(size_t)128 * SNO], g_atl[(size_t)128 * SNO];
__device__ __align__(16) __nv_bfloat16 g_oh[(size_t)BB * SNO],  g_ol[(size_t)BB * SNO];
__device__ float g_att[(size_t)128 * SNO];    // fp32 logits

// ---------------------------------------------------------------------------
__device__ __forceinline__ void mma16816(float* c, const uint32_t* a, const uint32_t* b) {
    asm volatile(
        "mma.sync.aligned.m16n8k16.row.col.f32.bf16.bf16.f32 "
        "{%0,%1,%2,%3}, {%4,%5,%6,%7}, {%8,%9}, {%0,%1,%2,%3};"
        : "+f"(c[0]), "+f"(c[1]), "+f"(c[2]), "+f"(c[3])
        : "r"(a[0]), "r"(a[1]), "r"(a[2]), "r"(a[3]), "r"(b[0]), "r"(b[1]));
}
__device__ __forceinline__ void split_bf16(float x, __nv_bfloat16& h, __nv_bfloat16& l) {
    h = __float2bfloat16_rn(x);
    l = __float2bfloat16_rn(x - __bfloat162float(h));
}
__device__ __forceinline__ uint32_t sw_off(int row, int chunk) {
    return (uint32_t)((row << 6) + (((chunk) ^ ((row >> 1) & 3)) << 4));
}
__device__ __forceinline__ void ldm_x4(uint32_t& r0, uint32_t& r1, uint32_t& r2, uint32_t& r3,
                                       uint32_t a) {
    asm volatile("ldmatrix.sync.aligned.m8n8.x4.shared.b16 {%0,%1,%2,%3}, [%4];"
                 : "=r"(r0), "=r"(r1), "=r"(r2), "=r"(r3) : "r"(a));
}
__device__ __forceinline__ void cp16(uint32_t dst, const void* src, int sz) {
    asm volatile("cp.async.cg.shared.global [%0], [%1], 16, %2;"
                 :: "r"(dst), "l"(src), "r"(sz) : "memory");
}
__device__ __forceinline__ void cp_commit() {
    asm volatile("cp.async.commit_group;" ::: "memory");
}
template <int N>
__device__ __forceinline__ void cp_wait() {
    asm volatile("cp.async.wait_group %0;" :: "n"(N) : "memory");
}

#define TSTRIDE 136   // stash row stride in bf16 elems (272B, 16B-aligned)

// ---------------------------------------------------------------------------
// Pre-split GEMM, tile 128m x 64n, 3 CTAs/SM. 3-stage cp.async ring,
// one barrier/step. C = A @ B^T.
// CONV: A rows shifted by (kpos-1), zero-padded; B +shift*SNO; 48 K-steps.
// EPI: 0 none, 1 (v+bias-m)*s+b then ReLU, 2 LeakyReLU(0.2)
// OUT: 0 = split bf16 planes, 1 = fp32, 2 = split planes + TRANSPOSED planes
// ---------------------------------------------------------------------------
template <int EPI, int OUT, bool CONV>
__global__ void __launch_bounds__(256, 3) gemm_p(
    const __nv_bfloat16* __restrict__ Ah, const __nv_bfloat16* __restrict__ Al,
    int lda, long sA1, long sA2,
    const __nv_bfloat16* __restrict__ Bh, const __nv_bfloat16* __restrict__ Bl,
    int ldb, long sB1, long sB2,
    float* __restrict__ Cf, __nv_bfloat16* __restrict__ Ch, __nv_bfloat16* __restrict__ Cl,
    int ldc, long sC1, long sC2,
    int K, int zdiv,
    const float* __restrict__ bias,
    const float* __restrict__ bng, const float* __restrict__ bnb,
    const float* __restrict__ bnm, const float* __restrict__ bnv,
    __nv_bfloat16* __restrict__ Th, __nv_bfloat16* __restrict__ Tl, int ldt, long sT1, long sT2)
{
    __shared__ __align__(16) unsigned char sm[NSTAGE * BUFSZ];
    const uint32_t smb = (uint32_t)__cvta_generic_to_shared(sm);

    const int z  = blockIdx.z;
    const int z1 = z / zdiv;
    const int z2 = z - z1 * zdiv;
    Ah += z1 * sA1 + z2 * sA2;  Al += z1 * sA1 + z2 * sA2;
    Bh += z1 * sB1 + z2 * sB2;  Bl += z1 * sB1 + z2 * sB2;
    if (OUT == 1) Cf += z1 * sC1 + z2 * sC2;
    else { Ch += z1 * sC1 + z2 * sC2; Cl += z1 * sC1 + z2 * sC2; }
    if (OUT == 2) { Th += z1 * sT1 + z2 * sT2; Tl += z1 * sT1 + z2 * sT2; }

    const int m0 = blockIdx.y * 128;
    const int n0 = blockIdx.x * 64;
    const int tid = threadIdx.x;

    const int w    = tid >> 5;
    const int lane = tid & 31;
    const int gq   = lane >> 2;
    const int tig  = lane & 3;
    const int wm   = (w >> 1) * 32;  // 4 m-warps over 128
    const int wn   = (w & 1) * 32;   // 2 n-warps over 64

    float acc[2][4][4];
#pragma unroll
    for (int i = 0; i < 2; i++)
#pragma unroll
        for (int j = 0; j < 4; j++)
#pragma unroll
            for (int q = 0; q < 4; q++) acc[i][j][q] = 0.f;

    const int steps = CONV ? 48 : (K >> 5);

    auto stageAsync = [&](int s, uint32_t bufo) {
        int k0, shift;
        if (CONV) { shift = s >> 4; k0 = (s & 15) * KC; }
        else      { shift = 0;      k0 = s * KC; }
        const uint32_t base = smb + bufo;
        // A planes: 512 chunk-pairs, 2 per thread
#pragma unroll
        for (int rep = 0; rep < 2; rep++) {
            const int c   = tid + rep * 256;
            const int row = c >> 2;
            const int kc  = c & 3;
            const uint32_t off = sw_off(row, kc);
            long arow = m0 + row;
            int sz = 16;
            if (CONV) {
                int rs = m0 + row + shift - 1;
                if (rs < 0 || rs >= NNODE) { sz = 0; rs = 0; }
                arow = rs;
            }
            const long so = arow * (long)lda + k0 + kc * 8;
            cp16(base + off,        Ah + so, sz);
            cp16(base + 8192 + off, Al + so, sz);
        }
        // B planes: 256 chunk-pairs, 1 per thread
        {
            const int row = tid >> 2;   // 0..63
            const int kc  = tid & 3;
            const uint32_t off = sw_off(row, kc);
            const long so = (CONV ? (long)shift * (long)SNO : 0L)
                          + (long)(n0 + row) * (long)ldb + k0 + kc * 8;
            cp16(base + 16384 + off, Bh + so, 16);
            cp16(base + 20480 + off, Bl + so, 16);
        }
    };

    auto compute = [&](uint32_t bufo) {
        const uint32_t AHs = smb + bufo, ALs = AHs + 8192;
        const uint32_t BHs = AHs + 16384, BLs = AHs + 20480;
#pragma unroll
        for (int ks = 0; ks < 2; ks++) {
            const int kc = ks * 2;
            uint32_t afh[2][4], afl[2][4];
            const int arow = wm + (lane & 15);
            const int achk = kc + (lane >> 4);
#pragma unroll
            for (int mt = 0; mt < 2; mt++) {
                const uint32_t off = sw_off(arow + mt * 16, achk);
                ldm_x4(afh[mt][0], afh[mt][1], afh[mt][2], afh[mt][3], AHs + off);
                ldm_x4(afl[mt][0], afl[mt][1], afl[mt][2], afl[mt][3], ALs + off);
            }
            const int brow_b = wn + (lane & 7) + ((lane >> 4) << 3);
            const int bchk = kc + ((lane >> 3) & 1);
#pragma unroll
            for (int ntp = 0; ntp < 2; ntp++) {
                const uint32_t off = sw_off(brow_b + ntp * 16, bchk);
                uint32_t bh[4], bl[4];
                ldm_x4(bh[0], bh[1], bh[2], bh[3], BHs + off);
                ldm_x4(bl[0], bl[1], bl[2], bl[3], BLs + off);
                // pass-outer ordering; per-acc order stays hh -> hl -> lh.
#pragma unroll
                for (int pass = 0; pass < 3; pass++) {
#pragma unroll
                    for (int hf = 0; hf < 2; hf++) {
                        const int nt = ntp * 2 + hf;
                        uint32_t bfh[2] = {bh[hf * 2], bh[hf * 2 + 1]};
                        uint32_t bfl[2] = {bl[hf * 2], bl[hf * 2 + 1]};
#pragma unroll
                        for (int mt = 0; mt < 2; mt++) {
                            if (pass == 0)      mma16816(acc[mt][nt], afh[mt], bfh);
                            else if (pass == 1) mma16816(acc[mt][nt], afh[mt], bfl);
                            else                mma16816(acc[mt][nt], afl[mt], bfh);
                        }
                    }
                }
            }
        }
    };

    // ---- 3-stage ring, one barrier per step ----
    stageAsync(0, 0); cp_commit();
    stageAsync(1, BUFSZ); cp_commit();
    for (int s = 0; s < steps; s++) {
        cp_wait<1>();
        __syncthreads();
        if (s + 2 < steps) stageAsync(s + 2, (uint32_t)((s + 2) % NSTAGE) * BUFSZ);
        cp_commit();
        compute((uint32_t)(s % NSTAGE) * BUFSZ);
    }

    // ---- epilogue ----
    __nv_bfloat16* sth = reinterpret_cast<__nv_bfloat16*>(sm);
    __nv_bfloat16* stl = reinterpret_cast<__nv_bfloat16*>(sm + 64 * TSTRIDE * 2);
    if (OUT == 2) __syncthreads();

#pragma unroll
    for (int mt = 0; mt < 2; mt++) {
        const long r0 = m0 + wm + mt * 16 + gq;
        const long r1 = r0 + 8;
#pragma unroll
        for (int nt = 0; nt < 4; nt++) {
            const int cb = n0 + wn + nt * 8 + 2 * tig;
            float v[4] = {acc[mt][nt][0], acc[mt][nt][1], acc[mt][nt][2], acc[mt][nt][3]};
            if (EPI == 1) {
#pragma unroll
                for (int q = 0; q < 4; q++) {
                    const int n = cb + (q & 1);
                    float sc = bng[n] * rsqrtf(bnv[n] + EPSV);
                    v[q] = (v[q] + bias[n] - bnm[n]) * sc + bnb[n];
                    v[q] = fmaxf(v[q], 0.f);
                }
            } else if (EPI == 2) {
#pragma unroll
                for (int q = 0; q < 4; q++) v[q] = (v[q] > 0.f) ? v[q] : 0.2f * v[q];
            }
            if (OUT == 1) {
                *reinterpret_cast<float2*>(Cf + r0 * ldc + cb) = make_float2(v[0], v[1]);
                *reinterpret_cast<float2*>(Cf + r1 * ldc + cb) = make_float2(v[2], v[3]);
            } else {
                __nv_bfloat16 h0, l0, h1, l1, h2, l2, h3, l3;
                split_bf16(v[0], h0, l0); split_bf16(v[1], h1, l1);
                split_bf16(v[2], h2, l2); split_bf16(v[3], h3, l3);
                __nv_bfloat162 ph, pl;
                ph.x = h0; ph.y = h1; pl.x = l0; pl.y = l1;
                *reinterpret_cast<__nv_bfloat162*>(Ch + r0 * ldc + cb) = ph;
                *reinterpret_cast<__nv_bfloat162*>(Cl + r0 * ldc + cb) = pl;
                ph.x = h2; ph.y = h3; pl.x = l2; pl.y = l3;
                *reinterpret_cast<__nv_bfloat162*>(Ch + r1 * ldc + cb) = ph;
                *reinterpret_cast<__nv_bfloat162*>(Cl + r1 * ldc + cb) = pl;
                if (OUT == 2) {
                    const int lr0 = (int)(r0 - m0), lr1 = (int)(r1 - m0);
                    const int lc = cb - n0;
                    sth[(lc + 0) * TSTRIDE + lr0] = h0;
                    sth[(lc + 1) * TSTRIDE + lr0] = h1;
                    sth[(lc + 0) * TSTRIDE + lr1] = h2;
                    sth[(lc + 1) * TSTRIDE + lr1] = h3;
                    stl[(lc + 0) * TSTRIDE + lr0] = l0;
                    stl[(lc + 1) * TSTRIDE + lr0] = l1;
                    stl[(lc + 0) * TSTRIDE + lr1] = l2;
                    stl[(lc + 1) * TSTRIDE + lr1] = l3;
                }
            }
        }
    }

    if (OUT == 2) {
        __syncthreads();
        const int col = tid >> 2;        // 0..63 (C column = T row)
        const int q   = tid & 3;         // m-quarter
        const long trow = (long)(n0 + col) * ldt + m0 + q * 32;
#pragma unroll
        for (int i = 0; i < 4; i++) {
            *reinterpret_cast<uint4*>(Th + trow + i * 8) =
                *reinterpret_cast<const uint4*>(&sth[col * TSTRIDE + q * 32 + i * 8]);
            *reinterpret_cast<uint4*>(Tl + trow + i * 8) =
                *reinterpret_cast<const uint4*>(&stl[col * TSTRIDE + q * 32 + i * 8]);
        }
    }
}

// ---------------------------------------------------------------------------
// prep: split raw fp32 inputs into bf16 hi/lo planes (vectorized, 4/thread)
// ---------------------------------------------------------------------------
__global__ void prep(const float* __restrict__ x, const float* __restrict__ adj,
                     const float* __restrict__ gc_w, const float* __restrict__ gat_w,
                     const float* __restrict__ conv_w)
{
    long i = ((long)blockIdx.x * 256 + threadIdx.x) * 4;
    __nv_bfloat16 h[4], l[4];

    auto storePlanes = [&](__nv_bfloat16* dh, __nv_bfloat16* dl, long idx) {
        __nv_bfloat162 p0, p1;
        p0.x = h[0]; p0.y = h[1]; p1.x = h[2]; p1.y = h[3];
        *reinterpret_cast<__nv_bfloat162*>(dh + idx)     = p0;
        *reinterpret_cast<__nv_bfloat162*>(dh + idx + 2) = p1;
        p0.x = l[0]; p0.y = l[1]; p1.x = l[2]; p1.y = l[3];
        *reinterpret_cast<__nv_bfloat162*>(dl + idx)     = p0;
        *reinterpret_cast<__nv_bfloat162*>(dl + idx + 2) = p1;
    };

    if (i < (long)NX) {
        float4 v = *reinterpret_cast<const float4*>(x + i);
        split_bf16(v.x, h[0], l[0]); split_bf16(v.y, h[1], l[1]);
        split_bf16(v.z, h[2], l[2]); split_bf16(v.w, h[3], l[3]);
        storePlanes(g_xph, g_xpl, i); return;
    }
    i -= NX;
    if (i < (long)NADJ) {
        float4 v = *reinterpret_cast<const float4*>(adj + i);
        split_bf16(v.x, h[0], l[0]); split_bf16(v.y, h[1], l[1]);
        split_bf16(v.z, h[2], l[2]); split_bf16(v.w, h[3], l[3]);
        storePlanes(g_adjh, g_adjl, i); return;
    }
    i -= NADJ;
    if (i < (long)NGW) {       // gwt[d][c] = gc_w[c][d]; 4 consecutive c
        long d = i >> 8, c = i & 255;
#pragma unroll
        for (int q = 0; q < 4; q++) split_bf16(gc_w[(c + q) * 512 + d], h[q], l[q]);
        storePlanes(g_gwth, g_gwtl, i); return;
    }
    i -= NGW;
    if (i < (long)NGAT) {
        float4 v = *reinterpret_cast<const float4*>(gat_w + i);
        split_bf16(v.x, h[0], l[0]); split_bf16(v.y, h[1], l[1]);
        split_bf16(v.z, h[2], l[2]); split_bf16(v.w, h[3], l[3]);
        storePlanes(g_gath, g_gatl, i); return;
    }
    i -= NGAT;
    if (i < (long)NCW) {       // cw[kpos][co][ci]; 4 consecutive ci
        long kpos = i / 262144, r = i % 262144;
        long co = r >> 9, ci = r & 511;
#pragma unroll
        for (int q = 0; q < 4; q++)
            split_bf16(conv_w[co * 1536 + (ci + q) * 3 + kpos], h[q], l[q]);
        storePlanes(g_cwh, g_cwl, i); return;
    }
}

// ---------------------------------------------------------------------------
// Row softmax over 512 fp32 -> split bf16 planes (shuffle reductions)
// ---------------------------------------------------------------------------
__global__ void softmax512(const float* __restrict__ att,
                           __nv_bfloat16* __restrict__ oh, __nv_bfloat16* __restrict__ ol)
{
    __shared__ float wmax[8], wsum[8];
    const long row = blockIdx.x;
    const float* p = att + row * 512;
    const int t = threadIdx.x;
    const int w = t >> 5, ln = t & 31;
    float a = p[t];
    float b = p[t + 256];
    float mx = fmaxf(a, b);
#pragma unroll
    for (int o = 16; o; o >>= 1) mx = fmaxf(mx, __shfl_xor_sync(0xffffffffu, mx, o));
    if (ln == 0) wmax[w] = mx;
    __syncthreads();
    float m = fmaxf(fmaxf(fmaxf(wmax[0], wmax[1]), fmaxf(wmax[2], wmax[3])),
                    fmaxf(fmaxf(wmax[4], wmax[5]), fmaxf(wmax[6], wmax[7])));
    float e0 = __expf(a - m);
    float e1 = __expf(b - m);
    float sm = e0 + e1;
#pragma unroll
    for (int o = 16; o; o >>= 1) sm += __shfl_xor_sync(0xffffffffu, sm, o);
    if (ln == 0) wsum[w] = sm;
    __syncthreads();
    float tot = (wsum[0] + wsum[1]) + (wsum[2] + wsum[3])
              + (wsum[4] + wsum[5]) + (wsum[6] + wsum[7]);
    const float inv = 1.f / tot;
    __nv_bfloat16 h, l;
    split_bf16(e0 * inv, h, l);
    oh[row * 512 + t] = h; ol[row * 512 + t] = l;
    split_bf16(e1 * inv, h, l);
    oh[row * 512 + t + 256] = h; ol[row * 512 + t + 256] = l;
}

// ---------------------------------------------------------------------------
extern "C" void kernel_launch(void* const* d_in, const int* in_sizes, int n_in,
                              void* d_out, int out_size)
{
    const float* x      = (const float*)d_in[0];
    const float* adj    = (const float*)d_in[1];
    const float* gc_w   = (const float*)d_in[2];
    const float* gc_b   = (const float*)d_in[3];
    const float* bn1g   = (const float*)d_in[4];
    const float* bn1b   = (const float*)d_in[5];
    const float* bn1m   = (const float*)d_in[6];
    const float* bn1v   = (const float*)d_in[7];
    const float* gat_w  = (const float*)d_in[8];
    const float* conv_w = (const float*)d_in[9];
    const float* conv_b = (const float*)d_in[10];
    const float* bn2g   = (const float*)d_in[11];
    const float* bn2b   = (const float*)d_in[12];
    const float* bn2m   = (const float*)d_in[13];
    const float* bn2v   = (const float*)d_in[14];
    float* out = (float*)d_out;

    __nv_bfloat16 *xph, *xpl, *adjh, *adjl, *gwth, *gwtl, *gath, *gatl, *cwh, *cwl;
    __nv_bfloat16 *suth, *sutl, *gh, *gl, *hhh, *hhl, *hth, *htl, *ath, *atl, *oh, *ol;
    float* att;
    cudaGetSymbolAddress((void**)&xph, g_xph);   cudaGetSymbolAddress((void**)&xpl, g_xpl);
    cudaGetSymbolAddress((void**)&adjh, g_adjh); cudaGetSymbolAddress((void**)&adjl, g_adjl);
    cudaGetSymbolAddress((void**)&gwth, g_gwth); cudaGetSymbolAddress((void**)&gwtl, g_gwtl);
    cudaGetSymbolAddress((void**)&gath, g_gath); cudaGetSymbolAddress((void**)&gatl, g_gatl);
    cudaGetSymbolAddress((void**)&cwh, g_cwh);   cudaGetSymbolAddress((void**)&cwl, g_cwl);
    cudaGetSymbolAddress((void**)&suth, g_suth); cudaGetSymbolAddress((void**)&sutl, g_sutl);
    cudaGetSymbolAddress((void**)&gh, g_gh);     cudaGetSymbolAddress((void**)&gl, g_gl);
    cudaGetSymbolAddress((void**)&hhh, g_hhh);   cudaGetSymbolAddress((void**)&hhl, g_hhl);
    cudaGetSymbolAddress((void**)&hth, g_hth);   cudaGetSymbolAddress((void**)&htl, g_htl);
    cudaGetSymbolAddress((void**)&ath, g_ath);   cudaGetSymbolAddress((void**)&atl, g_atl);
    cudaGetSymbolAddress((void**)&oh, g_oh);     cudaGetSymbolAddress((void**)&ol, g_ol);
    cudaGetSymbolAddress((void**)&att, g_att);

    const long total_prep = (long)(NX + NADJ + NGW + NGAT + NCW);

    // 0) split inputs (4 elems/thread)
    prep<<<(unsigned)((total_prep / 4 + 255) / 256), 256>>>(x, adj, gc_w, gat_w, conv_w);

    // 1) supT[d][bn] = sum_c gwt[d][c] * x[bn][c]   (M=512, N=16384, K=256)
    gemm_p<0, 0, false><<<dim3(256, 4, 1), 256>>>(
        gwth, gwtl, 256, 0, 0,
        xph, xpl, 256, 0, 0,
        nullptr, suth, sutl, 16384, 0, 0,
        256, 1, nullptr, nullptr, nullptr, nullptr, nullptr,
        nullptr, nullptr, 0, 0, 0);

    // 2) g[b] = relu(bn1(adj @ sup + gc_b))
    gemm_p<1, 0, false><<<dim3(8, 4, BB), 256>>>(
        adjh, adjl, 512, 0, 0,
        suth, sutl, 16384, 512, 0,
        nullptr, gh, gl, 512, (long)SNO, 0,
        512, 1, gc_b, bn1g, bn1b, bn1m, bn1v,
        nullptr, nullptr, 0, 0, 0);

    // 3) hh[b] = g @ gat_w^T   (+ fused transpose -> hhT)
    gemm_p<0, 2, false><<<dim3(8, 4, BB), 256>>>(
        gh, gl, 512, (long)SNO, 0,
        gath, gatl, 512, 0, 0,
        nullptr, hhh, hhl, 512, (long)SNO, 0,
        512, 1, nullptr, nullptr, nullptr, nullptr, nullptr,
        hth, htl, 512, (long)SNO, 0);

    // 4) logits[b,h] = leaky(hh_h @ hh_h^T)
    gemm_p<2, 1, false><<<dim3(8, 4, BB * NHEAD), 256>>>(
        hhh, hhl, 512, (long)SNO, 128,
        hhh, hhl, 512, (long)SNO, 128,
        att, nullptr, nullptr, 512, (long)(4 * SNO), (long)SNO,
        128, NHEAD, nullptr, nullptr, nullptr, nullptr, nullptr,
        nullptr, nullptr, 0, 0, 0);

    // 5) softmax -> split att planes
    softmax512<<<128 * 512, 256>>>(att, ath, atl);

    // 6) o[b,h] = att @ hh_h
    gemm_p<0, 0, false><<<dim3(2, 4, BB * NHEAD), 256>>>(
        ath, atl, 512, (long)(4 * SNO), (long)SNO,
        hth, htl, 512, (long)SNO, (long)(128 * 512),
        nullptr, oh, ol, 512, (long)SNO, 128,
        512, NHEAD, nullptr, nullptr, nullptr, nullptr, nullptr,
        nullptr, nullptr, 0, 0, 0);

    // 7) conv1d(k=3,p=1) + bias + bn2 + relu -> out fp32
    gemm_p<1, 1, true><<<dim3(8, 4, BB), 256>>>(
        oh, ol, 512, (long)SNO, 0,
        cwh, cwl, 512, 0, 0,
        out, nullptr, nullptr, 512, (long)SNO, 0,
        3 * 512, 1, conv_b, bn2g, bn2b, bn2m, bn2v,
        nullptr, nullptr, 0, 0, 0);
}